// round 5
// baseline (speedup 1.0000x reference)
#include <cuda_runtime.h>

#define BB 512
#define TT 4096
#define HH 32
#define NBLK (TT / 32)       // 128 blocks of 32 timesteps
#define RSTR 36              // ring row stride in floats (144B, 16B-aligned!)
#define RING_FLOATS (33 * RSTR)          // one ring: 33 rows
#define SMEM_FLOATS (2 * 8 * RING_FLOATS)
#define SMEM_BYTES (SMEM_FLOATS * 4)     // 76,032 B < 227KB carveout

static __device__ __forceinline__ unsigned long long pk2(float lo, float hi) {
    unsigned long long r;
    asm("mov.b64 %0, {%1,%2};" : "=l"(r) : "f"(lo), "f"(hi));
    return r;
}
static __device__ __forceinline__ void upk2(unsigned long long v, float& lo, float& hi) {
    asm("mov.b64 {%0,%1}, %2;" : "=f"(lo), "=f"(hi) : "l"(v));
}
static __device__ __forceinline__ void fma2(unsigned long long& d, unsigned long long a, unsigned long long b) {
    asm("fma.rn.f32x2 %0, %1, %2, %0;" : "+l"(d) : "l"(a), "l"(b));
}
static __device__ __forceinline__ unsigned long long add2(unsigned long long a, unsigned long long b) {
    unsigned long long r;
    asm("add.rn.f32x2 %0, %1, %2;" : "=l"(r) : "l"(a), "l"(b));
    return r;
}
static __device__ __forceinline__ unsigned int smem_u32(const void* p) {
    unsigned int a;
    asm("{ .reg .u64 t; cvta.to.shared.u64 t, %1; cvt.u32.u64 %0, t; }" : "=r"(a) : "l"(p));
    return a;
}

__global__ __launch_bounds__(512, 1)
void rnn_fused_kernel(const float* __restrict__ x,
                      const float* __restrict__ h0,
                      const float* __restrict__ W_ih,
                      const float* __restrict__ b_ih,
                      const float* __restrict__ W_hh,
                      const float* __restrict__ b_hh,
                      const float* __restrict__ W_out,
                      const float* __restrict__ b_out,
                      float* __restrict__ out,
                      int write_h) {
    extern __shared__ __align__(16) float sring[];

    const int wid  = threadIdx.x >> 5;
    const int lane = threadIdx.x & 31;
    const int p    = wid & 7;                 // chain id within CTA, 0..7
    const int b    = blockIdx.x * 8 + p;      // batch chain

    // ring base for [buf][p]
    float* ring0 = sring + (0 * 8 + p) * RING_FLOATS;
    float* ring1 = sring + (1 * 8 + p) * RING_FLOATS;

    if (wid >= 8) {
        // ── MAIN (recurrence) warp: wid 8..15 → 2 per SMSP, hi arbiter priority ──
        unsigned long long Wr[16];
        const float4* wp = reinterpret_cast<const float4*>(W_hh + lane * HH);
#pragma unroll
        for (int k = 0; k < 8; k++) {
            float4 v = wp[k];
            Wr[2 * k]     = pk2(v.x, v.y);
            Wr[2 * k + 1] = pk2(v.z, v.w);
        }
        const float wih  = W_ih[lane];
        const float bias = b_ih[lane] + b_hh[lane];

        float h = h0[b * HH + lane];
        const float* xb = x + (long)b * TT;
        float xv = xb[lane];

        for (int k = 0; k < NBLK; k++) {
            float xv_next = (k + 1 < NBLK) ? xb[k * 32 + 32 + lane] : 0.0f;

            float* base = (k & 1) ? ring1 : ring0;
            const unsigned int bs = smem_u32(base) + lane * 4u;

#pragma unroll
            for (int s = 0; s < 32; s++) {
                float xt = __shfl_sync(0xffffffffu, xv, s);
                float xp = fmaf(xt, wih, bias);

                // Publish entering state h_{t0+s} into ring row s.
                asm volatile("st.shared.f32 [%0], %1;"
                             :: "r"(bs + s * (RSTR * 4)), "f"(h) : "memory");

                const ulonglong2* hp =
                    reinterpret_cast<const ulonglong2*>(base + s * RSTR);
                ulonglong2 q0 = hp[0], q1 = hp[1], q2 = hp[2], q3 = hp[3];
                ulonglong2 q4 = hp[4], q5 = hp[5], q6 = hp[6], q7 = hp[7];

                // Single accumulator: fma2 rt(4) >= lat(4), so no RAW stall,
                // and it removes the combine add2 from the tail.
                unsigned long long a0 = pk2(xp, 0.0f);
                fma2(a0, Wr[0],  q0.x); fma2(a0, Wr[1],  q0.y);
                fma2(a0, Wr[2],  q1.x); fma2(a0, Wr[3],  q1.y);
                fma2(a0, Wr[4],  q2.x); fma2(a0, Wr[5],  q2.y);
                fma2(a0, Wr[6],  q3.x); fma2(a0, Wr[7],  q3.y);
                fma2(a0, Wr[8],  q4.x); fma2(a0, Wr[9],  q4.y);
                fma2(a0, Wr[10], q5.x); fma2(a0, Wr[11], q5.y);
                fma2(a0, Wr[12], q6.x); fma2(a0, Wr[13], q6.y);
                fma2(a0, Wr[14], q7.x); fma2(a0, Wr[15], q7.y);
                float lo, hi; upk2(a0, lo, hi);
                float z = lo + hi;
                asm("tanh.approx.f32 %0, %1;" : "=f"(h) : "f"(z));  // MUFU.TANH
            }
            // Row 32: state after the last step (for y_{t0+31}).
            asm volatile("st.shared.f32 [%0], %1;"
                         :: "r"(bs + 32 * (RSTR * 4)), "f"(h) : "memory");
            // Hand block k to helper; also confirms helper freed this buffer.
            asm volatile("bar.sync %0, %1;" :: "r"(p), "r"(64) : "memory");

            xv = xv_next;
        }

        if (write_h) {
            out[(long)BB * TT + b * HH + lane] = h;   // h_state [1,B,H]
        }
    } else {
        // ── HELPER (output projection) warp: wid 0..7 ──
        unsigned long long Wo[16];
        const float4* op = reinterpret_cast<const float4*>(W_out);
#pragma unroll
        for (int k = 0; k < 8; k++) {
            float4 v = op[k];
            Wo[2 * k]     = pk2(v.x, v.y);
            Wo[2 * k + 1] = pk2(v.z, v.w);
        }
        const float bout = b_out[0];
        float* ob = out + (long)b * TT;

        for (int k = 0; k < NBLK; k++) {
            asm volatile("bar.sync %0, %1;" :: "r"(p), "r"(64) : "memory");

            // Lane s computes y_{t0+s} = W_out . h_{t0+s+1} + b_out from row s+1.
            float* base = (k & 1) ? ring1 : ring0;
            const float* row = base + (lane + 1) * RSTR;

            unsigned long long y0 = pk2(bout, 0.0f), y1 = 0ull;
#pragma unroll
            for (int j = 0; j < 8; j++) {
                float4 v = *reinterpret_cast<const float4*>(row + 4 * j);
                fma2(y0, Wo[2 * j],     pk2(v.x, v.y));
                fma2(y1, Wo[2 * j + 1], pk2(v.z, v.w));
            }
            unsigned long long ys = add2(y0, y1);
            float ylo, yhi; upk2(ys, ylo, yhi);

            ob[k * 32 + lane] = ylo + yhi;   // coalesced 128B store
        }
    }
}

extern "C" void kernel_launch(void* const* d_in, const int* in_sizes, int n_in,
                              void* d_out, int out_size) {
    const float* x     = (const float*)d_in[0];
    const float* h0    = (const float*)d_in[1];
    const float* W_ih  = (const float*)d_in[2];
    const float* b_ih  = (const float*)d_in[3];
    const float* W_hh  = (const float*)d_in[4];
    const float* b_hh  = (const float*)d_in[5];
    const float* W_out = (const float*)d_in[6];
    const float* b_out = (const float*)d_in[7];
    float* out = (float*)d_out;

    int write_h = (out_size >= BB * TT + BB * HH) ? 1 : 0;

    static int attr_set = 0;
    if (!attr_set) {
        cudaFuncSetAttribute(rnn_fused_kernel,
                             cudaFuncAttributeMaxDynamicSharedMemorySize,
                             SMEM_BYTES);
        attr_set = 1;
    }

    rnn_fused_kernel<<<BB / 8, 512, SMEM_BYTES>>>(x, h0, W_ih, b_ih, W_hh, b_hh,
                                                  W_out, b_out, out, write_h);
}

// round 6
// speedup vs baseline: 1.3563x; 1.3563x over previous
#include <cuda_runtime.h>

#define BB 512
#define TT 4096
#define HH 32
#define NBLK (TT / 32)   // 128 blocks of 32 timesteps
#define RSTR 36          // padded row stride in floats (144B, 16B-aligned)

static __device__ __forceinline__ unsigned long long pk2(float lo, float hi) {
    unsigned long long r;
    asm("mov.b64 %0, {%1,%2};" : "=l"(r) : "f"(lo), "f"(hi));
    return r;
}
static __device__ __forceinline__ void upk2(unsigned long long v, float& lo, float& hi) {
    asm("mov.b64 {%0,%1}, %2;" : "=f"(lo), "=f"(hi) : "l"(v));
}
static __device__ __forceinline__ void fma2(unsigned long long& d, unsigned long long a, unsigned long long b) {
    asm("fma.rn.f32x2 %0, %1, %2, %0;" : "+l"(d) : "l"(a), "l"(b));
}
static __device__ __forceinline__ unsigned long long add2(unsigned long long a, unsigned long long b) {
    unsigned long long r;
    asm("add.rn.f32x2 %0, %1, %2;" : "=l"(r) : "l"(a), "l"(b));
    return r;
}
static __device__ __forceinline__ unsigned int smem_u32(const void* p) {
    unsigned int a;
    asm("{ .reg .u64 t; cvta.to.shared.u64 t, %1; cvt.u32.u64 %0, t; }" : "=r"(a) : "l"(p));
    return a;
}

// SMEM rings: [double-buffer][chain][33 h-vectors][padded 36 floats]
__shared__ __align__(16) float g_bufs[2][4][33][RSTR];

__global__ __launch_bounds__(256, 1)
void rnn_fused_kernel(const float* __restrict__ x,
                      const float* __restrict__ h0,
                      const float* __restrict__ W_ih,
                      const float* __restrict__ b_ih,
                      const float* __restrict__ W_hh,
                      const float* __restrict__ b_hh,
                      const float* __restrict__ W_out,
                      const float* __restrict__ b_out,
                      float* __restrict__ out,
                      int write_h) {
    const int wid  = threadIdx.x >> 5;
    const int lane = threadIdx.x & 31;
    const int p    = wid & 3;                 // chain id 0..3
    const int b    = blockIdx.x * 4 + p;      // batch chain

    if (wid >= 4) {
        // ── MAIN (recurrence) warp: wid 4..7 → exactly 1 per SMSP ──
        unsigned long long Wr[16];
        const float4* wp = reinterpret_cast<const float4*>(W_hh + lane * HH);
#pragma unroll
        for (int k = 0; k < 8; k++) {
            float4 v = wp[k];
            Wr[2 * k]     = pk2(v.x, v.y);
            Wr[2 * k + 1] = pk2(v.z, v.w);
        }
        const float wih  = W_ih[lane];
        const float bias = b_ih[lane] + b_hh[lane];

        float h = h0[b * HH + lane];
        const float* xb = x + (long)b * TT;
        float xv = xb[lane];

        for (int k = 0; k < NBLK; k++) {
            float xv_next = (k + 1 < NBLK) ? xb[k * 32 + 32 + lane] : 0.0f;

            float* base = &g_bufs[k & 1][p][0][0];
            const unsigned int bs = smem_u32(base) + lane * 4u;

            // Hoist the entire x-projection for this 32-step block OFF the
            // serial chain: 32 shfl+fmaf burst here instead of one shfl
            // (lat 26) heading every step's dependency chain.
            float xp[32];
#pragma unroll
            for (int s = 0; s < 32; s++) {
                xp[s] = fmaf(__shfl_sync(0xffffffffu, xv, s), wih, bias);
            }

#pragma unroll
            for (int s = 0; s < 32; s++) {
                // Publish entering state h_{t0+s} into ring row s.
                asm volatile("st.shared.f32 [%0], %1;"
                             :: "r"(bs + s * (RSTR * 4)), "f"(h) : "memory");

                const ulonglong2* hp =
                    reinterpret_cast<const ulonglong2*>(base + s * RSTR);
                ulonglong2 q0 = hp[0], q1 = hp[1], q2 = hp[2], q3 = hp[3];
                ulonglong2 q4 = hp[4], q5 = hp[5], q6 = hp[6], q7 = hp[7];

                // Two accumulators: consecutive fma2 independent → issue at
                // rt2 with gap 4 ≥ lat 4 per accumulator. (Single-acc
                // serializes at 4cyc/op — R5 post-mortem.)
                unsigned long long a0 = pk2(xp[s], 0.0f), a1 = 0ull;
                fma2(a0, Wr[0],  q0.x); fma2(a1, Wr[1],  q0.y);
                fma2(a0, Wr[2],  q1.x); fma2(a1, Wr[3],  q1.y);
                fma2(a0, Wr[4],  q2.x); fma2(a1, Wr[5],  q2.y);
                fma2(a0, Wr[6],  q3.x); fma2(a1, Wr[7],  q3.y);
                fma2(a0, Wr[8],  q4.x); fma2(a1, Wr[9],  q4.y);
                fma2(a0, Wr[10], q5.x); fma2(a1, Wr[11], q5.y);
                fma2(a0, Wr[12], q6.x); fma2(a1, Wr[13], q6.y);
                fma2(a0, Wr[14], q7.x); fma2(a1, Wr[15], q7.y);
                unsigned long long ss = add2(a0, a1);
                float lo, hi; upk2(ss, lo, hi);
                float z = lo + hi;
                asm("tanh.approx.f32 %0, %1;" : "=f"(h) : "f"(z));  // MUFU.TANH
            }
            // Row 32: state after the last step (for y_{t0+31}).
            asm volatile("st.shared.f32 [%0], %1;"
                         :: "r"(bs + 32 * (RSTR * 4)), "f"(h) : "memory");
            // Hand block k to helper; also confirms helper freed this buffer.
            asm volatile("bar.sync %0, %1;" :: "r"(p), "r"(64) : "memory");

            xv = xv_next;
        }

        if (write_h) {
            out[(long)BB * TT + b * HH + lane] = h;   // h_state [1,B,H]
        }
    } else {
        // ── HELPER (output projection) warp: wid 0..3 ──
        unsigned long long Wo[16];
        const float4* op = reinterpret_cast<const float4*>(W_out);
#pragma unroll
        for (int k = 0; k < 8; k++) {
            float4 v = op[k];
            Wo[2 * k]     = pk2(v.x, v.y);
            Wo[2 * k + 1] = pk2(v.z, v.w);
        }
        const float bout = b_out[0];
        float* ob = out + (long)b * TT;

        for (int k = 0; k < NBLK; k++) {
            asm volatile("bar.sync %0, %1;" :: "r"(p), "r"(64) : "memory");

            // Lane s computes y_{t0+s} = W_out . h_{t0+s+1} + b_out from row s+1.
            const float* row = &g_bufs[k & 1][p][lane + 1][0];

            unsigned long long y0 = pk2(bout, 0.0f), y1 = 0ull;
#pragma unroll
            for (int j = 0; j < 8; j++) {
                float4 v = *reinterpret_cast<const float4*>(row + 4 * j);
                fma2(y0, Wo[2 * j],     pk2(v.x, v.y));
                fma2(y1, Wo[2 * j + 1], pk2(v.z, v.w));
            }
            unsigned long long ys = add2(y0, y1);
            float ylo, yhi; upk2(ys, ylo, yhi);

            ob[k * 32 + lane] = ylo + yhi;   // coalesced 128B store
        }
    }
}

extern "C" void kernel_launch(void* const* d_in, const int* in_sizes, int n_in,
                              void* d_out, int out_size) {
    const float* x     = (const float*)d_in[0];
    const float* h0    = (const float*)d_in[1];
    const float* W_ih  = (const float*)d_in[2];
    const float* b_ih  = (const float*)d_in[3];
    const float* W_hh  = (const float*)d_in[4];
    const float* b_hh  = (const float*)d_in[5];
    const float* W_out = (const float*)d_in[6];
    const float* b_out = (const float*)d_in[7];
    float* out = (float*)d_out;

    int write_h = (out_size >= BB * TT + BB * HH) ? 1 : 0;

    rnn_fused_kernel<<<BB / 4, 256>>>(x, h0, W_ih, b_ih, W_hh, b_hh,
                                      W_out, b_out, out, write_h);
}